// round 11
// baseline (speedup 1.0000x reference)
#include <cuda_runtime.h>
#include <cuda_bf16.h>

#define B_   8
#define N_   1024
#define IN_  512
#define H_   8
#define SUP_ 64
#define BH_  (B_*H_)      // 64
#define ROWS_ (B_*N_)     // 8192

// Scratch (no cudaMalloc allowed)
__device__ float4 g_inputsv[BH_ * N_ * SUP_ / 4];   // [bh][n][o] plain, 16.8 MB
__device__ float4 g_xdup[ROWS_ * IN_ * 2 / 4];      // [row][2k] dup pairs, 33.5 MB
__device__ float4 g_s4[BH_ * N_];                   // {s, e^s, e^{0.01s}, 0}
__device__ float4 g_t4[BH_ * N_];                   // {t, e^t, e^{0.01t}, 0}

// ---------- helpers ----------
__device__ __forceinline__ unsigned long long pack2(float x, float y){
    unsigned long long r;
    asm("mov.b64 %0, {%1, %2};" : "=l"(r) : "f"(x), "f"(y));
    return r;
}
__device__ __forceinline__ void fma2(unsigned long long &d, unsigned long long a, unsigned long long b){
    asm("fma.rn.f32x2 %0, %1, %2, %0;" : "+l"(d) : "l"(a), "l"(b));
}
__device__ __forceinline__ float2 unpack2(unsigned long long v){
    float2 f;
    asm("mov.b64 {%0, %1}, %2;" : "=f"(f.x), "=f"(f.y) : "l"(v));
    return f;
}
__device__ __forceinline__ unsigned smem_u32(const void* p){
    unsigned a;
    asm("{ .reg .u64 t; cvta.to.shared.u64 t, %1; cvt.u32.u64 %0, t; }" : "=r"(a) : "l"(p));
    return a;
}
__device__ __forceinline__ void cpa16(unsigned dst, const void* src){
    asm volatile("cp.async.cg.shared.global [%0], [%1], 16;" :: "r"(dst), "l"(src));
}
__device__ __forceinline__ void cpa_commit(){ asm volatile("cp.async.commit_group;"); }
__device__ __forceinline__ void cpa_wait0(){ asm volatile("cp.async.wait_group 0;"); }

// ---------- polynomial exp (262K calls, fc kernel only) ----------
__device__ __forceinline__ float fast_exp(float x){
    float t = x * 1.4426950408889634f;
    t = fmaxf(t, -80.0f);
    float r = t + 12582912.0f;
    float f = t - (r - 12582912.0f);
    int   n = __float_as_int(r) - 0x4B400000;
    float p = 1.33335581e-3f;
    p = fmaf(p, f, 9.61812911e-3f);
    p = fmaf(p, f, 5.55041087e-2f);
    p = fmaf(p, f, 2.40226507e-1f);
    p = fmaf(p, f, 6.93147181e-1f);
    p = fmaf(p, f, 1.0f);
    return __int_as_float(__float_as_int(p) + (n << 23));
}

// 64-col half-shift swizzle -> conflict-free 8-chunk LDS.128 (stride 68)
#define WOFF(c) ((c) + (((c) >> 5) << 2))

// ============================================================
// Kernel 0: duplicate X pairs  g_xdup[row][2k]=[2k+1]=X[row][k]
// ============================================================
__global__ __launch_bounds__(256) void dupx_kernel(const float* __restrict__ X){
    int i = blockIdx.x * 256 + threadIdx.x;          // over 1M float4
    float4 v = ((const float4*)X)[i];
    float4* o = g_xdup + 2 * (size_t)i;
    o[0] = make_float4(v.x, v.x, v.y, v.y);
    o[1] = make_float4(v.z, v.z, v.w, v.w);
}

// ============================================================
// Kernel A: per-head projection  inputs[bh][n][o] = X[b,n,:] @ W[h,:,o]
// CTA: 128 rows x 64 cols (one head), 256 threads, 4 rows x 8 cols/thread.
// A-operand: LDS.64 of dup X pairs (no movs). B: 2 conflict-free LDS.128.
// cols-in-u64 acc (16 u64). k-tile 16, cp.async double-buffered.
// ============================================================
#define PXT (128 * 36)            // X dup buffer floats (row stride 36)
#define PWT (16 * 68)             // W buffer floats
#define PROJ_SMEM ((2 * PXT + 2 * PWT) * 4)   // 45568 B

__global__ __launch_bounds__(256, 4) void proj_kernel(const float* __restrict__ W){
    extern __shared__ __align__(16) float sm[];
    float* Xs = sm;                    // [2][128][36]  (dup pairs: [row][2k..2k+31])
    float* Ws = sm + 2 * PXT;          // [2][16][68]   WOFF-swizzled

    const int h   = blockIdx.y;
    const int R0  = blockIdx.x * 128;
    const int tid = threadIdx.x;
    const int colg = tid & 7, rowg = tid >> 3;
    const int c0  = colg * 8;
    const int r0  = rowg * 4;
    const int wo  = WOFF(c0);

    const float* Wh   = W + (size_t)h * (IN_ * SUP_);
    const float* xdup = (const float*)g_xdup;

    const unsigned xs_u = smem_u32(Xs);
    const unsigned ws_u = smem_u32(Ws);

    auto stage = [&](int kt, int p){
        // X dup tile: 128 rows x 32 dup-floats = 1024 float4, 4 per thread
#pragma unroll
        for (int j = 0; j < 4; j++){
            int fid = tid + j * 256;
            int row = fid >> 3, ch = (fid & 7) * 4;
            cpa16(xs_u + (unsigned)(p * PXT + row * 36 + ch) * 4u,
                  xdup + (size_t)(R0 + row) * (2 * IN_) + 2 * kt + ch);
        }
        // W tile: 16 k x 64 cols = 256 float4, 1 per thread
        {
            int kk = tid >> 4, cc = (tid & 15) * 4;
            cpa16(ws_u + (unsigned)(p * PWT + kk * 68 + WOFF(cc)) * 4u,
                  Wh + (size_t)(kt + kk) * SUP_ + cc);
        }
        cpa_commit();
    };

    unsigned long long acc[4][4];      // [row i][col-pair cp] = (c0+2cp, c0+2cp+1)
#pragma unroll
    for (int i = 0; i < 4; i++)
#pragma unroll
        for (int c = 0; c < 4; c++) acc[i][c] = 0ull;

    stage(0, 0);

    for (int t = 0; t < IN_ / 16; t++){
        const int p = t & 1;
        cpa_wait0();
        __syncthreads();
        if (t + 1 < IN_ / 16) stage((t + 1) * 16, p ^ 1);

        const float* Xp = Xs + p * PXT + r0 * 36;
        const float* Wp = Ws + p * PWT;
#pragma unroll
        for (int k = 0; k < 16; k++){
            const float* wk = &Wp[k * 68 + wo];
            ulonglong2 w0 = *(const ulonglong2*)(wk);       // cols c0..c0+3
            ulonglong2 w1 = *(const ulonglong2*)(wk + 4);   // cols c0+4..c0+7
#pragma unroll
            for (int i = 0; i < 4; i++){
                unsigned long long xa = *(const unsigned long long*)(Xp + i * 36 + 2 * k);
                fma2(acc[i][0], xa, w0.x);
                fma2(acc[i][1], xa, w0.y);
                fma2(acc[i][2], xa, w1.x);
                fma2(acc[i][3], xa, w1.y);
            }
        }
    }

    float* gi = (float*)g_inputsv;
#pragma unroll
    for (int i = 0; i < 4; i++){
        int R = R0 + r0 + i;
        int b = R >> 10, n = R & 1023;
        float2 v0 = unpack2(acc[i][0]);
        float2 v1 = unpack2(acc[i][1]);
        float2 v2 = unpack2(acc[i][2]);
        float2 v3 = unpack2(acc[i][3]);
        float* dst = gi + ((size_t)(b * H_ + h) * N_ + n) * SUP_ + c0;
        *(float4*)dst       = make_float4(v0.x, v0.y, v1.x, v1.y);
        *(float4*)(dst + 4) = make_float4(v2.x, v2.y, v3.x, v3.y);
    }
}

// ============================================================
// Kernel B: s/t logit pieces + factored exponentials
// ============================================================
__global__ __launch_bounds__(256) void fc_kernel(const float* __restrict__ w1, const float* __restrict__ b1,
                                                 const float* __restrict__ w2, const float* __restrict__ b2){
    int rid  = blockIdx.x * 8 + (threadIdx.x >> 5);   // 0..65535
    int lane = threadIdx.x & 31;
    int h    = (rid >> 10) & 7;
    const float* row = (const float*)g_inputsv + (size_t)rid * 64;
    float v0 = row[lane], v1 = row[lane + 32];
    float d1 = v0 * w1[h * 64 + lane] + v1 * w1[h * 64 + 32 + lane];
    float d2 = v0 * w2[h * 64 + lane] + v1 * w2[h * 64 + 32 + lane];
#pragma unroll
    for (int off = 16; off >= 1; off >>= 1){
        d1 += __shfl_xor_sync(0xffffffffu, d1, off);
        d2 += __shfl_xor_sync(0xffffffffu, d2, off);
    }
    if (lane == 0){
        float s = d1 + b1[h];
        float t = d2 + b2[h];
        g_s4[rid] = make_float4(s, fast_exp(s), fast_exp(0.01f * s), 0.f);
        g_t4[rid] = make_float4(t, fast_exp(t), fast_exp(0.01f * t), 0.f);
    }
}

// ============================================================
// Kernel C: fused masked-softmax attention + aggregation + relu
// CTA = one (b,h) x 128 rows, 256 threads, 4 rows x 8 cols/thread.
// e-phase stores DUP pairs via STS.64 (free dup); fma phase:
// 4 LDS.64 (e-dup) + 2 LDS.128 (x plain, WOFF) + 16 FFMA2, zero movs.
// Denominator folded into e-phase registers; one reduction at end.
// ============================================================
#define MT_ 32
#define ESTR 258                               // e_s dup row stride (floats)
#define AIN (MT_ * 68)                         // in_s buffer floats
#define ATTN_SMEM ((2*AIN + MT_*ESTR + 2*MT_*4 + 128*4) * 4)   // 53504 B

__global__ __launch_bounds__(256, 4) void attn_kernel(const float* __restrict__ A,
                                                      float* __restrict__ out){
    extern __shared__ __align__(16) float smA[];
    float*  in_s = smA;                               // [2][32][68]
    float*  e_s  = smA + 2 * AIN;                     // [32][258] dup pairs
    float4* t4_s = (float4*)(smA + 2 * AIN + MT_ * ESTR);   // [2][32]
    float4* s4_s = t4_s + 2 * MT_;                    // [128]

    const int bh  = blockIdx.y;
    const int b   = bh >> 3, h = bh & 7;
    const int R0  = blockIdx.x * 128;
    const int tid = threadIdx.x;
    const int colg = tid & 7, rowg = tid >> 3;
    const int c0  = colg * 8;
    const int r0  = rowg * 4;                         // 4 rows, shared by e-phase & fma
    const int wo  = WOFF(c0);
    const int em0 = colg * 4;                         // e-phase m-group

    if (tid < 128) s4_s[tid] = g_s4[(size_t)bh * N_ + R0 + tid];

    const float*  Ab     = A + ((size_t)b * N_ + R0) * N_;
    const float*  inbase = (const float*)g_inputsv + (size_t)bh * (N_ * SUP_);
    const float4* t4g    = g_t4 + (size_t)bh * N_;

    const unsigned in_u = smem_u32(in_s);
    const unsigned t4_u = smem_u32(t4_s);

    auto stage = [&](int mt, int p){
#pragma unroll
        for (int j = 0; j < 2; j++){
            int fid = tid + j * 256;
            int m = fid >> 4, c = (fid & 15) * 4;
            cpa16(in_u + (unsigned)(p * AIN + m * 68 + WOFF(c)) * 4u,
                  inbase + (size_t)(mt + m) * SUP_ + c);
        }
        if (tid < MT_) cpa16(t4_u + (unsigned)(p * MT_ + tid) * 16u, t4g + mt + tid);
        cpa_commit();
    };

    unsigned long long acc[4][4];      // [row i][col-pair]
#pragma unroll
    for (int i = 0; i < 4; i++)
#pragma unroll
        for (int c = 0; c < 4; c++) acc[i][c] = 0ull;
    float dreg[4] = {0.f, 0.f, 0.f, 0.f};

    stage(0, 0);

    for (int t = 0; t < N_ / MT_; t++){
        const int p  = t & 1;
        const int mt = t * MT_;
        cpa_wait0();
        __syncthreads();                    // in_s[p]/t4[p] ready; e_s free

        // e-phase: this thread's 4 rows x 4 m; dup-stored via STS.64
        {
            const float4* t4p = t4_s + p * MT_;
            float4 t0 = t4p[em0 + 0];
            float4 t1 = t4p[em0 + 1];
            float4 t2 = t4p[em0 + 2];
            float4 t3 = t4p[em0 + 3];
#pragma unroll
            for (int i = 0; i < 4; i++){
                float4 sr = s4_s[r0 + i];
                float4 a4 = *(const float4*)(Ab + (size_t)(r0 + i) * N_ + mt + em0);
                float thr = -sr.x;
                float e0 = a4.x * ((t0.x >= thr) ? (sr.y * t0.y) : (sr.z * t0.z));
                float e1 = a4.y * ((t1.x >= thr) ? (sr.y * t1.y) : (sr.z * t1.z));
                float e2 = a4.z * ((t2.x >= thr) ? (sr.y * t2.y) : (sr.z * t2.z));
                float e3 = a4.w * ((t3.x >= thr) ? (sr.y * t3.y) : (sr.z * t3.z));
                dreg[i] += (e0 + e1) + (e2 + e3);
                *(unsigned long long*)(e_s + (em0 + 0) * ESTR + 2 * (r0 + i)) = pack2(e0, e0);
                *(unsigned long long*)(e_s + (em0 + 1) * ESTR + 2 * (r0 + i)) = pack2(e1, e1);
                *(unsigned long long*)(e_s + (em0 + 2) * ESTR + 2 * (r0 + i)) = pack2(e2, e2);
                *(unsigned long long*)(e_s + (em0 + 3) * ESTR + 2 * (r0 + i)) = pack2(e3, e3);
            }
        }
        if (t + 1 < N_ / MT_) stage(mt + MT_, p ^ 1);
        __syncthreads();                    // e_s written

        // fma phase
        const float* inp = in_s + p * AIN;
#pragma unroll 8
        for (int m = 0; m < MT_; m++){
            const float* ep = e_s + m * ESTR + 2 * r0;
            unsigned long long e0 = *(const unsigned long long*)(ep);
            unsigned long long e1 = *(const unsigned long long*)(ep + 2);
            unsigned long long e2 = *(const unsigned long long*)(ep + 4);
            unsigned long long e3 = *(const unsigned long long*)(ep + 6);
            const float* xr = inp + m * 68 + wo;
            ulonglong2 x0 = *(const ulonglong2*)(xr);       // cols c0..c0+3
            ulonglong2 x1 = *(const ulonglong2*)(xr + 4);   // cols c0+4..c0+7
            fma2(acc[0][0], e0, x0.x); fma2(acc[0][1], e0, x0.y);
            fma2(acc[0][2], e0, x1.x); fma2(acc[0][3], e0, x1.y);
            fma2(acc[1][0], e1, x0.x); fma2(acc[1][1], e1, x0.y);
            fma2(acc[1][2], e1, x1.x); fma2(acc[1][3], e1, x1.y);
            fma2(acc[2][0], e2, x0.x); fma2(acc[2][1], e2, x0.y);
            fma2(acc[2][2], e2, x1.x); fma2(acc[2][3], e2, x1.y);
            fma2(acc[3][0], e3, x0.x); fma2(acc[3][1], e3, x0.y);
            fma2(acc[3][2], e3, x1.x); fma2(acc[3][3], e3, x1.y);
        }
    }

    // denominator reduction: reuse e_s as [128 rows][8 m-group partials]
    __syncthreads();
    float* dp = e_s;
#pragma unroll
    for (int i = 0; i < 4; i++) dp[(r0 + i) * 8 + colg] = dreg[i];
    __syncthreads();

#pragma unroll
    for (int i = 0; i < 4; i++){
        const float* dr = dp + (r0 + i) * 8;
        float dsum = ((dr[0] + dr[1]) + (dr[2] + dr[3])) + ((dr[4] + dr[5]) + (dr[6] + dr[7]));
        float inv = 1.0f / dsum;
        float2 v0 = unpack2(acc[i][0]);
        float2 v1 = unpack2(acc[i][1]);
        float2 v2 = unpack2(acc[i][2]);
        float2 v3 = unpack2(acc[i][3]);
        float* op = out + ((size_t)(b * N_ + R0 + r0 + i)) * (H_ * SUP_) + h * SUP_ + c0;
        *(float4*)op       = make_float4(fmaxf(v0.x,0.f)*inv, fmaxf(v0.y,0.f)*inv,
                                         fmaxf(v1.x,0.f)*inv, fmaxf(v1.y,0.f)*inv);
        *(float4*)(op + 4) = make_float4(fmaxf(v2.x,0.f)*inv, fmaxf(v2.y,0.f)*inv,
                                         fmaxf(v3.x,0.f)*inv, fmaxf(v3.y,0.f)*inv);
    }
}

// ============================================================
extern "C" void kernel_launch(void* const* d_in, const int* in_sizes, int n_in,
                              void* d_out, int out_size){
    // match inputs by element count: A=8388608, X=4194304, W=262144, w1/w2=512, b1/b2=8
    const float *A = nullptr, *X = nullptr, *W = nullptr;
    const float *w1 = nullptr, *w2 = nullptr, *b1 = nullptr, *b2 = nullptr;
    for (int i = 0; i < n_in; i++){
        const float* p = (const float*)d_in[i];
        switch (in_sizes[i]){
            case 8388608: A = p; break;
            case 4194304: X = p; break;
            case 262144:  W = p; break;
            case 512:     (w1 ? w2 : w1) = p; break;
            case 8:       (b1 ? b2 : b1) = p; break;
            default: break;
        }
    }
    float* out = (float*)d_out;

    cudaFuncSetAttribute(proj_kernel, cudaFuncAttributeMaxDynamicSharedMemorySize, PROJ_SMEM);
    cudaFuncSetAttribute(attn_kernel, cudaFuncAttributeMaxDynamicSharedMemorySize, ATTN_SMEM);

    dupx_kernel<<<ROWS_ * IN_ / 4 / 256, 256>>>(X);
    proj_kernel<<<dim3(ROWS_ / 128, H_), 256, PROJ_SMEM>>>(W);
    fc_kernel<<<BH_ * N_ / 8, 256>>>(w1, b1, w2, b2);
    attn_kernel<<<dim3(N_ / 128, BH_), 256, ATTN_SMEM>>>(A, out);
}

// round 15
// speedup vs baseline: 1.3435x; 1.3435x over previous
#include <cuda_runtime.h>
#include <cuda_bf16.h>

#define B_   8
#define N_   1024
#define IN_  512
#define H_   8
#define SUP_ 64
#define BH_  (B_*H_)      // 64
#define ROWS_ (B_*N_)     // 8192

// Scratch (no cudaMalloc allowed). float4-typed for guaranteed 16B alignment.
__device__ float4 g_inputsv[BH_ * N_ * SUP_ / 4];   // [bh][n][o] 16.8 MB
__device__ float4 g_s4[BH_ * N_];                   // {s, e^s, e^{0.01s}, 0}
__device__ float4 g_t4[BH_ * N_];                   // {t, e^t, e^{0.01t}, 0}

// ---------- helpers ----------
__device__ __forceinline__ unsigned long long pack2(float x, float y){
    unsigned long long r;
    asm("mov.b64 %0, {%1, %2};" : "=l"(r) : "f"(x), "f"(y));
    return r;
}
__device__ __forceinline__ void fma2(unsigned long long &d, unsigned long long a, unsigned long long b){
    asm("fma.rn.f32x2 %0, %1, %2, %0;" : "+l"(d) : "l"(a), "l"(b));
}
__device__ __forceinline__ float2 unpack2(unsigned long long v){
    float2 f;
    asm("mov.b64 {%0, %1}, %2;" : "=f"(f.x), "=f"(f.y) : "l"(v));
    return f;
}
__device__ __forceinline__ unsigned smem_u32(const void* p){
    unsigned a;
    asm("{ .reg .u64 t; cvta.to.shared.u64 t, %1; cvt.u32.u64 %0, t; }" : "=r"(a) : "l"(p));
    return a;
}
__device__ __forceinline__ void cpa16(unsigned dst, const void* src){
    asm volatile("cp.async.cg.shared.global [%0], [%1], 16;" :: "r"(dst), "l"(src));
}
__device__ __forceinline__ void cpa_commit(){ asm volatile("cp.async.commit_group;"); }
__device__ __forceinline__ void cpa_wait0(){ asm volatile("cp.async.wait_group 0;"); }

// ---------- polynomial exp (262K calls, fc kernel only) ----------
__device__ __forceinline__ float fast_exp(float x){
    float t = x * 1.4426950408889634f;
    t = fmaxf(t, -80.0f);
    float r = t + 12582912.0f;               // round-to-nearest via magic
    float f = t - (r - 12582912.0f);
    int   n = __float_as_int(r) - 0x4B400000;
    float p = 1.33335581e-3f;
    p = fmaf(p, f, 9.61812911e-3f);
    p = fmaf(p, f, 5.55041087e-2f);
    p = fmaf(p, f, 2.40226507e-1f);
    p = fmaf(p, f, 6.93147181e-1f);
    p = fmaf(p, f, 1.0f);
    return __int_as_float(__float_as_int(p) + (n << 23));
}

// Ws column swizzle: shift upper 32-col half by 4 floats -> conflict-free LDS.128
#define WOFF(c) ((c) + (((c) >> 5) << 2))

#define XSTR 36
#define XS_TILE (128 * XSTR)       // floats per X buffer
#define WS_TILE (32 * 72)          // floats per W buffer
#define PROJ_SMEM ((2 * XS_TILE + 2 * WS_TILE) * 4)   // 55296 bytes

// ============================================================
// Kernel A: per-head projection  inputs[bh][n][o] = X[b,n,:] @ W[h,:,o]
// CTA: 128 rows x 64 cols, 256 threads, 4 rows x 8 cols/thread.
// cp.async double-buffered staging: one wait+sync per k-tile.  (R9 verbatim)
// ============================================================
__global__ __launch_bounds__(256, 4) void proj_kernel(const float* __restrict__ X,
                                                      const float* __restrict__ W){
    extern __shared__ __align__(16) float sm[];
    float* Xs = sm;                       // [2][128][XSTR]
    float* Ws = sm + 2 * XS_TILE;         // [2][32][72]

    const int h   = blockIdx.y;
    const int R0  = blockIdx.x * 128;
    const int tid = threadIdx.x;
    const int tx  = tid & 7,  ty = tid >> 3;
    const int c0  = tx * 8,   r0 = ty * 4;
    const int wo  = WOFF(c0);

    const float* Wh = W + (size_t)h * (IN_ * SUP_);

    const int xrow = tid >> 3, xkq = (tid & 7) * 4;
    const int wkk  = tid >> 4, wcc = (tid & 15) * 4;
    const unsigned xs_base = smem_u32(Xs);
    const unsigned ws_base = smem_u32(Ws);

    auto stage = [&](int kt, int p){
        const float* xsrc = X + (size_t)(R0 + xrow) * IN_ + kt + xkq;
        unsigned     xdst = xs_base + (unsigned)(p * XS_TILE + xrow * XSTR + xkq) * 4u;
#pragma unroll
        for (int j = 0; j < 4; j++)
            cpa16(xdst + (unsigned)(j * 32 * XSTR) * 4u, xsrc + (size_t)(j * 32) * IN_);
        const float* wsrc = Wh + (size_t)(kt + wkk) * SUP_ + wcc;
        unsigned     wdst = ws_base + (unsigned)(p * WS_TILE + wkk * 72 + WOFF(wcc)) * 4u;
        cpa16(wdst, wsrc);
        cpa16(wdst + (unsigned)(16 * 72) * 4u, wsrc + (size_t)16 * SUP_);
        cpa_commit();
    };

    unsigned long long acc[4][4];
#pragma unroll
    for (int i = 0; i < 4; i++)
#pragma unroll
        for (int c = 0; c < 4; c++) acc[i][c] = 0ull;

    stage(0, 0);

    for (int t = 0; t < IN_ / 32; t++){
        const int p = t & 1;
        cpa_wait0();
        __syncthreads();
        if (t + 1 < IN_ / 32) stage((t + 1) * 32, p ^ 1);

        const float* Xp = Xs + p * XS_TILE;
        const float* Wp = Ws + p * WS_TILE;
#pragma unroll 8
        for (int k = 0; k < 32; k++){
            const float* wk = &Wp[k * 72 + wo];
            ulonglong2 w0 = *(const ulonglong2*)(wk);
            ulonglong2 w1 = *(const ulonglong2*)(wk + 4);
#pragma unroll
            for (int i = 0; i < 4; i++){
                float a = Xp[(r0 + i) * XSTR + k];
                unsigned long long aa = pack2(a, a);
                fma2(acc[i][0], aa, w0.x);
                fma2(acc[i][1], aa, w0.y);
                fma2(acc[i][2], aa, w1.x);
                fma2(acc[i][3], aa, w1.y);
            }
        }
    }

    float* gi = (float*)g_inputsv;
#pragma unroll
    for (int i = 0; i < 4; i++){
        int R = R0 + r0 + i;
        int b = R >> 10, n = R & 1023;
        float2 v0 = unpack2(acc[i][0]);
        float2 v1 = unpack2(acc[i][1]);
        float2 v2 = unpack2(acc[i][2]);
        float2 v3 = unpack2(acc[i][3]);
        float* dst = gi + ((size_t)(b * H_ + h) * N_ + n) * SUP_ + c0;
        *(float4*)dst       = make_float4(v0.x, v0.y, v1.x, v1.y);
        *(float4*)(dst + 4) = make_float4(v2.x, v2.y, v3.x, v3.y);
    }
}

// ============================================================
// Kernel B: s/t logit pieces + factored exponentials  (R9 verbatim)
// ============================================================
__global__ __launch_bounds__(256) void fc_kernel(const float* __restrict__ w1, const float* __restrict__ b1,
                                                 const float* __restrict__ w2, const float* __restrict__ b2){
    int rid  = blockIdx.x * 8 + (threadIdx.x >> 5);   // 0..65535
    int lane = threadIdx.x & 31;
    int h    = (rid >> 10) & 7;
    const float* row = (const float*)g_inputsv + (size_t)rid * 64;
    float v0 = row[lane], v1 = row[lane + 32];
    float d1 = v0 * w1[h * 64 + lane] + v1 * w1[h * 64 + 32 + lane];
    float d2 = v0 * w2[h * 64 + lane] + v1 * w2[h * 64 + 32 + lane];
#pragma unroll
    for (int off = 16; off >= 1; off >>= 1){
        d1 += __shfl_xor_sync(0xffffffffu, d1, off);
        d2 += __shfl_xor_sync(0xffffffffu, d2, off);
    }
    if (lane == 0){
        float s = d1 + b1[h];
        float t = d2 + b2[h];
        g_s4[rid] = make_float4(s, fast_exp(s), fast_exp(0.01f * s), 0.f);
        g_t4[rid] = make_float4(t, fast_exp(t), fast_exp(0.01f * t), 0.f);
    }
}

// ============================================================
// Kernel C: fused masked-softmax attention + aggregation + relu
// R9 structure (plain e_s STS.32, rows-in-u64 fma, cp.async dbuf),
// with the denominator folded into e-phase registers (denom pass removed).
// ============================================================
#define MT_ 32   // m-tile

__global__ __launch_bounds__(256, 4) void attn_kernel(const float* __restrict__ A,
                                                      float* __restrict__ out){
    __shared__ __align__(16) float  in_s[2][MT_ * 64];  // 16 KB
    __shared__ __align__(16) float  e_s[MT_ * 130];     // 16.25 KB
    __shared__ __align__(16) float4 s4_s[128];          // 2 KB
    __shared__ __align__(16) float4 t4_s[2][MT_];       // 1 KB
    __shared__ float dsum_s[128 * 8];                   // 4 KB [row][m-group]

    const int bh  = blockIdx.y;
    const int b   = bh >> 3, h = bh & 7;
    const int R0  = blockIdx.x * 128;
    const int tid = threadIdx.x;
    const int cg  = tid & 15;          // 16 col groups x 4 cols
    const int rg  = tid >> 4;          // 16 row groups x 8 rows
    const int c0  = cg * 4;
    const int rb  = rg * 8;

    // e-phase identity: row = erow0 + 32j (j<4), 4 m per row via float4 A
    const int erow0 = tid >> 3;        // 0..31
    const int em0   = (tid & 7) * 4;   // m base

    if (tid < 128) s4_s[tid] = g_s4[(size_t)bh * N_ + R0 + tid];

    const float*  Ab     = A + ((size_t)b * N_ + R0) * N_;
    const float*  inbase = (const float*)g_inputsv + (size_t)bh * (N_ * SUP_);
    const float4* t4g    = g_t4 + (size_t)bh * N_;

    const unsigned in_u  = smem_u32(in_s);
    const unsigned t4_u  = smem_u32(t4_s);

    auto stage = [&](int mt, int p){
        const float4* src = (const float4*)inbase + (size_t)mt * 16;
        unsigned dst = in_u + (unsigned)(p * MT_ * 64 + tid * 4) * 4u;
        cpa16(dst,              src + tid);
        cpa16(dst + 256u * 16u, src + tid + 256);
        if (tid < MT_) cpa16(t4_u + (unsigned)(p * MT_ + tid) * 16u, t4g + mt + tid);
        cpa_commit();
    };

    unsigned long long acc[4][4];
#pragma unroll
    for (int i = 0; i < 4; i++)
#pragma unroll
        for (int c = 0; c < 4; c++) acc[i][c] = 0ull;
    float dpart[4] = {0.f, 0.f, 0.f, 0.f};   // denom partials, rows erow0+32j

    stage(0, 0);

    for (int t = 0; t < N_ / MT_; t++){
        const int p  = t & 1;
        const int mt = t * MT_;
        cpa_wait0();
        __syncthreads();                       // tile data ready; prev reads done
        if (t + 1 < N_ / MT_) stage(mt + MT_, p ^ 1);

        // e-phase: 128 rows x 32 m (float4 A loads, coalesced); denom folded
#pragma unroll
        for (int j = 0; j < 4; j++){
            int row = erow0 + j * 32;
            float4 sr = s4_s[row];
            float4 a4 = *(const float4*)(Ab + (size_t)row * N_ + mt + em0);
            float4 t0 = t4_s[p][em0 + 0];
            float4 t1 = t4_s[p][em0 + 1];
            float4 t2 = t4_s[p][em0 + 2];
            float4 t3 = t4_s[p][em0 + 3];
            float thr = -sr.x;
            float e0 = a4.x * ((t0.x >= thr) ? (sr.y * t0.y) : (sr.z * t0.z));
            float e1 = a4.y * ((t1.x >= thr) ? (sr.y * t1.y) : (sr.z * t1.z));
            float e2 = a4.z * ((t2.x >= thr) ? (sr.y * t2.y) : (sr.z * t2.z));
            float e3 = a4.w * ((t3.x >= thr) ? (sr.y * t3.y) : (sr.z * t3.z));
            dpart[j] += (e0 + e1) + (e2 + e3);
            e_s[(em0 + 0) * 130 + row] = e0;
            e_s[(em0 + 1) * 130 + row] = e1;
            e_s[(em0 + 2) * 130 + row] = e2;
            e_s[(em0 + 3) * 130 + row] = e3;
        }
        __syncthreads();

        // fma phase: rows-in-u64
        const float* inp = in_s[p];
#pragma unroll 8
        for (int m = 0; m < MT_; m++){
            const float* ep = e_s + m * 130 + rb;
            unsigned long long e0 = *(const unsigned long long*)(ep);
            unsigned long long e1 = *(const unsigned long long*)(ep + 2);
            unsigned long long e2 = *(const unsigned long long*)(ep + 4);
            unsigned long long e3 = *(const unsigned long long*)(ep + 6);
            float4 xv = *(const float4*)&inp[m * 64 + c0];
            unsigned long long x0 = pack2(xv.x, xv.x);
            unsigned long long x1 = pack2(xv.y, xv.y);
            unsigned long long x2 = pack2(xv.z, xv.z);
            unsigned long long x3 = pack2(xv.w, xv.w);
            fma2(acc[0][0], e0, x0); fma2(acc[0][1], e0, x1);
            fma2(acc[0][2], e0, x2); fma2(acc[0][3], e0, x3);
            fma2(acc[1][0], e1, x0); fma2(acc[1][1], e1, x1);
            fma2(acc[1][2], e1, x2); fma2(acc[1][3], e1, x3);
            fma2(acc[2][0], e2, x0); fma2(acc[2][1], e2, x1);
            fma2(acc[2][2], e2, x2); fma2(acc[2][3], e2, x3);
            fma2(acc[3][0], e3, x0); fma2(acc[3][1], e3, x1);
            fma2(acc[3][2], e3, x2); fma2(acc[3][3], e3, x3);
        }
    }

    // publish denominator partials: dsum_s[row][m-group]
    __syncthreads();
#pragma unroll
    for (int j = 0; j < 4; j++)
        dsum_s[(erow0 + j * 32) * 8 + (tid & 7)] = dpart[j];
    __syncthreads();

#pragma unroll
    for (int i = 0; i < 4; i++){
        int r0 = rb + 2 * i;                       // local rows r0, r0+1
        const float* d0p = dsum_s + r0 * 8;
        const float* d1p = d0p + 8;
        float d0 = ((d0p[0]+d0p[1])+(d0p[2]+d0p[3])) + ((d0p[4]+d0p[5])+(d0p[6]+d0p[7]));
        float d1 = ((d1p[0]+d1p[1])+(d1p[2]+d1p[3])) + ((d1p[4]+d1p[5])+(d1p[6]+d1p[7]));
        float inv0 = 1.0f / d0, inv1 = 1.0f / d1;
        float2 v0 = unpack2(acc[i][0]);
        float2 v1 = unpack2(acc[i][1]);
        float2 v2 = unpack2(acc[i][2]);
        float2 v3 = unpack2(acc[i][3]);
        float* op0 = out + ((size_t)(b * N_ + R0 + r0)) * (H_ * SUP_) + h * SUP_ + c0;
        float* op1 = op0 + (H_ * SUP_);
        *(float4*)op0 = make_float4(fmaxf(v0.x, 0.f) * inv0, fmaxf(v1.x, 0.f) * inv0,
                                    fmaxf(v2.x, 0.f) * inv0, fmaxf(v3.x, 0.f) * inv0);
        *(float4*)op1 = make_float4(fmaxf(v0.y, 0.f) * inv1, fmaxf(v1.y, 0.f) * inv1,
                                    fmaxf(v2.y, 0.f) * inv1, fmaxf(v3.y, 0.f) * inv1);
    }
}

// ============================================================
extern "C" void kernel_launch(void* const* d_in, const int* in_sizes, int n_in,
                              void* d_out, int out_size){
    // match inputs by element count: A=8388608, X=4194304, W=262144, w1/w2=512, b1/b2=8
    const float *A = nullptr, *X = nullptr, *W = nullptr;
    const float *w1 = nullptr, *w2 = nullptr, *b1 = nullptr, *b2 = nullptr;
    for (int i = 0; i < n_in; i++){
        const float* p = (const float*)d_in[i];
        switch (in_sizes[i]){
            case 8388608: A = p; break;
            case 4194304: X = p; break;
            case 262144:  W = p; break;
            case 512:     (w1 ? w2 : w1) = p; break;
            case 8:       (b1 ? b2 : b1) = p; break;
            default: break;
        }
    }
    float* out = (float*)d_out;

    cudaFuncSetAttribute(proj_kernel, cudaFuncAttributeMaxDynamicSharedMemorySize, PROJ_SMEM);

    proj_kernel<<<dim3(ROWS_ / 128, H_), 256, PROJ_SMEM>>>(X, W);
    fc_kernel<<<BH_ * N_ / 8, 256>>>(w1, b1, w2, b2);
    attn_kernel<<<dim3(N_ / 128, BH_), 256>>>(A, out);
}

// round 17
// speedup vs baseline: 1.5990x; 1.1902x over previous
#include <cuda_runtime.h>
#include <cuda_bf16.h>

#define B_   8
#define N_   1024
#define IN_  512
#define H_   8
#define SUP_ 64
#define BH_  (B_*H_)      // 64
#define ROWS_ (B_*N_)     // 8192

// Scratch (no cudaMalloc allowed)
__device__ float4 g_inputsv[BH_ * N_ * SUP_ / 4];   // [bh][n][o] 16.8 MB
__device__ float4 g_s4[BH_ * N_];                   // {s, e^s, e^{0.01s}, 0}
__device__ float4 g_t4[BH_ * N_];                   // {t, e^t, e^{0.01t}, 0}
__device__ __nv_bfloat16 g_xhi[ROWS_ * IN_];        // 8.4 MB
__device__ __nv_bfloat16 g_xlo[ROWS_ * IN_];        // 8.4 MB
__device__ __nv_bfloat16 g_wthi[H_ * SUP_ * IN_];   // [h][c][k] transposed, 0.5 MB
__device__ __nv_bfloat16 g_wtlo[H_ * SUP_ * IN_];

// ---------- helpers ----------
__device__ __forceinline__ unsigned long long pack2(float x, float y){
    unsigned long long r;
    asm("mov.b64 %0, {%1, %2};" : "=l"(r) : "f"(x), "f"(y));
    return r;
}
__device__ __forceinline__ void fma2(unsigned long long &d, unsigned long long a, unsigned long long b){
    asm("fma.rn.f32x2 %0, %1, %2, %0;" : "+l"(d) : "l"(a), "l"(b));
}
__device__ __forceinline__ float2 unpack2(unsigned long long v){
    float2 f;
    asm("mov.b64 {%0, %1}, %2;" : "=f"(f.x), "=f"(f.y) : "l"(v));
    return f;
}
__device__ __forceinline__ unsigned smem_u32(const void* p){
    unsigned a;
    asm("{ .reg .u64 t; cvta.to.shared.u64 t, %1; cvt.u32.u64 %0, t; }" : "=r"(a) : "l"(p));
    return a;
}
__device__ __forceinline__ void cpa16(unsigned dst, const void* src){
    asm volatile("cp.async.cg.shared.global [%0], [%1], 16;" :: "r"(dst), "l"(src));
}
__device__ __forceinline__ void cpa_commit(){ asm volatile("cp.async.commit_group;"); }
__device__ __forceinline__ void cpa_wait0(){ asm volatile("cp.async.wait_group 0;"); }

__device__ __forceinline__ void ldsm4(unsigned* r, unsigned addr){
    asm volatile("ldmatrix.sync.aligned.m8n8.x4.shared.b16 {%0,%1,%2,%3}, [%4];"
                 : "=r"(r[0]), "=r"(r[1]), "=r"(r[2]), "=r"(r[3]) : "r"(addr));
}
__device__ __forceinline__ void mma16816(float* d, const unsigned* a, unsigned b0, unsigned b1){
    asm volatile("mma.sync.aligned.m16n8k16.row.col.f32.bf16.bf16.f32 "
                 "{%0,%1,%2,%3}, {%4,%5,%6,%7}, {%8,%9}, {%0,%1,%2,%3};"
                 : "+f"(d[0]), "+f"(d[1]), "+f"(d[2]), "+f"(d[3])
                 : "r"(a[0]), "r"(a[1]), "r"(a[2]), "r"(a[3]), "r"(b0), "r"(b1));
}

// ---------- polynomial exp (262K calls, fc kernel only) ----------
__device__ __forceinline__ float fast_exp(float x){
    float t = x * 1.4426950408889634f;
    t = fmaxf(t, -80.0f);
    float r = t + 12582912.0f;               // round-to-nearest via magic
    float f = t - (r - 12582912.0f);
    int   n = __float_as_int(r) - 0x4B400000;
    float p = 1.33335581e-3f;
    p = fmaf(p, f, 9.61812911e-3f);
    p = fmaf(p, f, 5.55041087e-2f);
    p = fmaf(p, f, 2.40226507e-1f);
    p = fmaf(p, f, 6.93147181e-1f);
    p = fmaf(p, f, 1.0f);
    return __int_as_float(__float_as_int(p) + (n << 23));
}

__device__ __forceinline__ unsigned pkbf(__nv_bfloat16 a, __nv_bfloat16 b){
    return (unsigned)__bfloat16_as_ushort(a) | ((unsigned)__bfloat16_as_ushort(b) << 16);
}

// ============================================================
// Kernel 0a: split X into bf16 hi/lo
// ============================================================
__global__ __launch_bounds__(256) void cvtx_kernel(const float* __restrict__ X){
    size_t idx = (size_t)blockIdx.x * 256 + threadIdx.x;     // over 1M float4
    float4 v = ((const float4*)X)[idx];
    __nv_bfloat16 h0 = __float2bfloat16_rn(v.x);
    __nv_bfloat16 h1 = __float2bfloat16_rn(v.y);
    __nv_bfloat16 h2 = __float2bfloat16_rn(v.z);
    __nv_bfloat16 h3 = __float2bfloat16_rn(v.w);
    __nv_bfloat16 l0 = __float2bfloat16_rn(v.x - __bfloat162float(h0));
    __nv_bfloat16 l1 = __float2bfloat16_rn(v.y - __bfloat162float(h1));
    __nv_bfloat16 l2 = __float2bfloat16_rn(v.z - __bfloat162float(h2));
    __nv_bfloat16 l3 = __float2bfloat16_rn(v.w - __bfloat162float(h3));
    *(uint2*)(g_xhi + idx * 4) = make_uint2(pkbf(h0, h1), pkbf(h2, h3));
    *(uint2*)(g_xlo + idx * 4) = make_uint2(pkbf(l0, l1), pkbf(l2, l3));
}

// ============================================================
// Kernel 0b: split W into bf16 hi/lo, TRANSPOSED per head: [h][c][k]
// grid (64, 8) = (c, h), 128 threads over k
// ============================================================
__global__ __launch_bounds__(128) void cvtw_kernel(const float* __restrict__ W){
    int c = blockIdx.x, h = blockIdx.y;
    int k = threadIdx.x * 4;
    const float* src = W + (size_t)h * (IN_ * SUP_) + c;
    __nv_bfloat16 hb[4], lb[4];
#pragma unroll
    for (int i = 0; i < 4; i++){
        float v = src[(size_t)(k + i) * SUP_];
        hb[i] = __float2bfloat16_rn(v);
        lb[i] = __float2bfloat16_rn(v - __bfloat162float(hb[i]));
    }
    size_t o = ((size_t)h * SUP_ + c) * IN_ + k;
    *(uint2*)(g_wthi + o) = make_uint2(pkbf(hb[0], hb[1]), pkbf(hb[2], hb[3]));
    *(uint2*)(g_wtlo + o) = make_uint2(pkbf(lb[0], lb[1]), pkbf(lb[2], lb[3]));
}

// ============================================================
// Kernel A: projection on mma.sync (HMMA bf16 split)
// CTA = (h, 128-row block): D[128,64] = X[128,512] @ W_h^T.
// 8 warps of 32x32; k-tile 32; cp.async double-buffered; XOR-chunk swizzle.
// ============================================================
#define A_TILE 8192                        // 128 rows x 64 B
#define B_TILE 4096                        // 64 rows x 64 B
#define BUFB (2 * A_TILE + 2 * B_TILE)     // 24576 per buffer
#define PROJ_SMEM (2 * BUFB)               // 49152

__global__ __launch_bounds__(256, 2) void proj_mma_kernel(float* dummy){
    extern __shared__ __align__(128) char sm[];
    const unsigned smb = smem_u32(sm);

    const int h   = blockIdx.y;
    const int R0  = blockIdx.x * 128;
    const int tid = threadIdx.x;
    const int wid = tid >> 5, L = tid & 31;
    const int wm  = wid >> 1, wn = wid & 1;           // 4 x 2 warp grid

    const __nv_bfloat16* xh = g_xhi + (size_t)R0 * IN_;
    const __nv_bfloat16* xl = g_xlo + (size_t)R0 * IN_;
    const __nv_bfloat16* wh = g_wthi + (size_t)h * SUP_ * IN_;
    const __nv_bfloat16* wl = g_wtlo + (size_t)h * SUP_ * IN_;

    // staging identities: A chunks (512 per tile): r = fid>>2, c = fid&3
    // B chunks (256 per tile): r = tid>>2, c = tid&3. Swizzle: c ^ ((r>>1)&3)
    auto stage = [&](int kt, int p){
        unsigned base = smb + p * BUFB;
#pragma unroll
        for (int j = 0; j < 2; j++){
            int fid = tid + j * 256;
            int r = fid >> 2, c = fid & 3;
            unsigned d = base + (unsigned)(r * 64 + ((c ^ ((r >> 1) & 3)) << 4));
            size_t s = (size_t)r * IN_ + kt + c * 8;
            cpa16(d,          xh + s);
            cpa16(d + A_TILE, xl + s);
        }
        {
            int r = tid >> 2, c = tid & 3;
            unsigned d = base + 2 * A_TILE + (unsigned)(r * 64 + ((c ^ ((r >> 1) & 3)) << 4));
            size_t s = (size_t)r * IN_ + kt + c * 8;
            cpa16(d,          wh + s);
            cpa16(d + B_TILE, wl + s);
        }
        cpa_commit();
    };

    // ldmatrix lane geometry
    const int arow = wm * 32 + (L & 7) + ((L >> 3) & 1) * 8;   // + mt*16
    const int kha  = L >> 4;                                   // A k-chunk half
    const int nrow = wn * 32 + (L & 7) + ((L >> 4) & 1) * 8;   // + ng*16
    const int khb  = (L >> 3) & 1;                             // B k-chunk half
    const int sxa  = (arow >> 1) & 3;                          // mt*16 doesn't change &3
    const int sxb  = (nrow >> 1) & 3;

    float acc[2][4][4];
#pragma unroll
    for (int mt = 0; mt < 2; mt++)
#pragma unroll
        for (int nt = 0; nt < 4; nt++)
#pragma unroll
            for (int q = 0; q < 4; q++) acc[mt][nt][q] = 0.f;

    stage(0, 0);

    for (int t = 0; t < IN_ / 32; t++){
        const int p = t & 1;
        cpa_wait0();
        __syncthreads();
        if (t + 1 < IN_ / 32) stage((t + 1) * 32, p ^ 1);

        unsigned abase = smb + p * BUFB;
        unsigned bbase = abase + 2 * A_TILE;

#pragma unroll
        for (int ks = 0; ks < 2; ks++){
            const int kc = ks * 2;
            unsigned ahi[2][4], alo[2][4], bhi[2][4], blo[2][4];
            unsigned ca = (unsigned)(((kc + kha) ^ sxa) << 4);
            unsigned cb = (unsigned)(((kc + khb) ^ sxb) << 4);
#pragma unroll
            for (int mt = 0; mt < 2; mt++){
                unsigned ra = (unsigned)((arow + mt * 16) * 64);
                ldsm4(ahi[mt], abase + ra + ca);
                ldsm4(alo[mt], abase + A_TILE + ra + ca);
            }
#pragma unroll
            for (int ng = 0; ng < 2; ng++){
                unsigned rb = (unsigned)((nrow + ng * 16) * 64);
                ldsm4(bhi[ng], bbase + rb + cb);
                ldsm4(blo[ng], bbase + B_TILE + rb + cb);
            }
#pragma unroll
            for (int mt = 0; mt < 2; mt++)
#pragma unroll
                for (int nt = 0; nt < 4; nt++){
                    int ng = nt >> 1, pr = (nt & 1) * 2;
                    mma16816(acc[mt][nt], ahi[mt], bhi[ng][pr], bhi[ng][pr + 1]);
                    mma16816(acc[mt][nt], ahi[mt], blo[ng][pr], blo[ng][pr + 1]);
                    mma16816(acc[mt][nt], alo[mt], bhi[ng][pr], bhi[ng][pr + 1]);
                }
        }
    }

    // epilogue: fragment c layout -> g_inputsv [bh][n][64]
    float* gi = (float*)g_inputsv;
#pragma unroll
    for (int mt = 0; mt < 2; mt++){
#pragma unroll
        for (int nt = 0; nt < 4; nt++){
            int Rr  = R0 + wm * 32 + mt * 16 + (L >> 2);
            int col = wn * 32 + nt * 8 + (L & 3) * 2;
            int b0i = Rr >> 10, n0i = Rr & 1023;
            int b1i = (Rr + 8) >> 10, n1i = (Rr + 8) & 1023;
            float* d0 = gi + ((size_t)(b0i * H_ + h) * N_ + n0i) * SUP_ + col;
            float* d1 = gi + ((size_t)(b1i * H_ + h) * N_ + n1i) * SUP_ + col;
            *(float2*)d0 = make_float2(acc[mt][nt][0], acc[mt][nt][1]);
            *(float2*)d1 = make_float2(acc[mt][nt][2], acc[mt][nt][3]);
        }
    }
}

// ============================================================
// Kernel B: s/t logit pieces + factored exponentials  (R15 verbatim)
// ============================================================
__global__ __launch_bounds__(256) void fc_kernel(const float* __restrict__ w1, const float* __restrict__ b1,
                                                 const float* __restrict__ w2, const float* __restrict__ b2){
    int rid  = blockIdx.x * 8 + (threadIdx.x >> 5);   // 0..65535
    int lane = threadIdx.x & 31;
    int h    = (rid >> 10) & 7;
    const float* row = (const float*)g_inputsv + (size_t)rid * 64;
    float v0 = row[lane], v1 = row[lane + 32];
    float d1 = v0 * w1[h * 64 + lane] + v1 * w1[h * 64 + 32 + lane];
    float d2 = v0 * w2[h * 64 + lane] + v1 * w2[h * 64 + 32 + lane];
#pragma unroll
    for (int off = 16; off >= 1; off >>= 1){
        d1 += __shfl_xor_sync(0xffffffffu, d1, off);
        d2 += __shfl_xor_sync(0xffffffffu, d2, off);
    }
    if (lane == 0){
        float s = d1 + b1[h];
        float t = d2 + b2[h];
        g_s4[rid] = make_float4(s, fast_exp(s), fast_exp(0.01f * s), 0.f);
        g_t4[rid] = make_float4(t, fast_exp(t), fast_exp(0.01f * t), 0.f);
    }
}

// ============================================================
// Kernel C: fused masked-softmax attention + aggregation + relu  (R15 verbatim)
// ============================================================
#define MT_ 32   // m-tile

__global__ __launch_bounds__(256, 4) void attn_kernel(const float* __restrict__ A,
                                                      float* __restrict__ out){
    __shared__ __align__(16) float  in_s[2][MT_ * 64];  // 16 KB
    __shared__ __align__(16) float  e_s[MT_ * 130];     // 16.25 KB
    __shared__ __align__(16) float4 s4_s[128];          // 2 KB
    __shared__ __align__(16) float4 t4_s[2][MT_];       // 1 KB
    __shared__ float dsum_s[128 * 8];                   // 4 KB [row][m-group]

    const int bh  = blockIdx.y;
    const int b   = bh >> 3, h = bh & 7;
    const int R0  = blockIdx.x * 128;
    const int tid = threadIdx.x;
    const int cg  = tid & 15;          // 16 col groups x 4 cols
    const int rg  = tid >> 4;          // 16 row groups x 8 rows
    const int c0  = cg * 4;
    const int rb  = rg * 8;

    const int erow0 = tid >> 3;        // 0..31
    const int em0   = (tid & 7) * 4;   // m base

    if (tid < 128) s4_s[tid] = g_s4[(size_t)bh * N_ + R0 + tid];

    const float*  Ab     = A + ((size_t)b * N_ + R0) * N_;
    const float*  inbase = (const float*)g_inputsv + (size_t)bh * (N_ * SUP_);
    const float4* t4g    = g_t4 + (size_t)bh * N_;

    const unsigned in_u  = smem_u32(in_s);
    const unsigned t4_u  = smem_u32(t4_s);

    auto stage = [&](int mt, int p){
        const float4* src = (const float4*)inbase + (size_t)mt * 16;
        unsigned dst = in_u + (unsigned)(p * MT_ * 64 + tid * 4) * 4u;
        cpa16(dst,              src + tid);
        cpa16(dst + 256u * 16u, src + tid + 256);
        if (tid < MT_) cpa16(t4_u + (unsigned)(p * MT_ + tid) * 16u, t4g + mt + tid);
        cpa_commit();
    };

    unsigned long long acc[4][4];
#pragma unroll
    for (int i = 0; i < 4; i++)
#pragma unroll
        for (int c = 0; c < 4; c++) acc[i][c] = 0ull;
    float dpart[4] = {0.f, 0.f, 0.f, 0.f};

    stage(0, 0);

    for (int t = 0; t < N_ / MT_; t++){
        const int p  = t & 1;
        const int mt = t * MT_;
        cpa_wait0();
        __syncthreads();
        if (t + 1 < N_ / MT_) stage(mt + MT_, p ^ 1);

#pragma unroll
        for (int j = 0; j < 4; j++){
            int row = erow0 + j * 32;
            float4 sr = s4_s[row];
            float4 a4 = *(const float4*)(Ab + (size_t)row * N_ + mt + em0);
            float4 t0 = t4_s[p][em0 + 0];
            float4 t1 = t4_s[p][em0 + 1];
            float4 t2 = t4_s[p][em0 + 2];
            float4 t3 = t4_s[p][em0 + 3];
            float thr = -sr.x;
            float e0 = a4.x * ((t0.x >= thr) ? (sr.y * t0.y) : (sr.z * t0.z));
            float e1 = a4.y * ((t1.x >= thr) ? (sr.y * t1.y) : (sr.z * t1.z));
            float e2 = a4.z * ((t2.x >= thr) ? (sr.y * t2.y) : (sr.z * t2.z));
            float e3 = a4.w * ((t3.x >= thr) ? (sr.y * t3.y) : (sr.z * t3.z));
            dpart[j] += (e0 + e1) + (e2 + e3);
            e_s[(em0 + 0) * 130 + row] = e0;
            e_s[(em0 + 1) * 130 + row] = e1;
            e_s[(em0 + 2) * 130 + row] = e2;
            e_s[(em0 + 3) * 130 + row] = e3;
        }
        __syncthreads();

        const float* inp = in_s[p];
#pragma unroll 8
        for (int m = 0; m < MT_; m++){
            const float* ep = e_s + m * 130 + rb;
            unsigned long long e0 = *(const unsigned long long*)(ep);
            unsigned long long e1 = *(const unsigned long long*)(ep + 2);
            unsigned long long e2 = *(const unsigned long long*)(ep + 4);
            unsigned long long e3 = *(const unsigned long long*)(ep + 6);
            float4 xv = *(const float4*)&inp[m * 64 + c0];
            unsigned long long x0 = pack2(xv.x, xv.x);
            unsigned long long x1 = pack2(xv.y, xv.y);
            unsigned long long x2 = pack2(xv.z, xv.z);
            unsigned long long x3 = pack2(xv.w, xv.w);
            fma2(acc[0][0], e0, x0); fma2(acc[0][1], e0, x1);
            fma2(acc[0][2], e0, x2); fma2(acc[0][3], e0, x3);
            fma2(acc[1][0], e1, x0); fma2(acc[1][1], e1, x1);
            fma2(acc[1][2], e1, x2); fma2(acc[1][3], e1, x3);
            fma2(acc[2][0], e2, x0); fma2(acc[2][1], e2, x1);
            fma2(acc[2][2], e2, x2); fma2(acc[2][3], e2, x3);
            fma2(acc[3][0], e3, x0); fma2(acc[3][1], e3, x1);
            fma2(acc[3][2], e3, x2); fma2(acc[3][3], e3, x3);
        }
    }

    __syncthreads();
#pragma unroll
    for (int j = 0; j < 4; j++)
        dsum_s[(erow0 + j * 32) * 8 + (tid & 7)] = dpart[j];
    __syncthreads();

#pragma unroll
    for (int i = 0; i < 4; i++){
        int r0 = rb + 2 * i;
        const float* d0p = dsum_s + r0 * 8;
        const float* d1p = d0p + 8;
        float d0 = ((d0p[0]+d0p[1])+(d0p[2]+d0p[3])) + ((d0p[4]+d0p[5])+(d0p[6]+d0p[7]));
        float d1 = ((d1p[0]+d1p[1])+(d1p[2]+d1p[3])) + ((d1p[4]+d1p[5])+(d1p[6]+d1p[7]));
        float inv0 = 1.0f / d0, inv1 = 1.0f / d1;
        float2 v0 = unpack2(acc[i][0]);
        float2 v1 = unpack2(acc[i][1]);
        float2 v2 = unpack2(acc[i][2]);
        float2 v3 = unpack2(acc[i][3]);
        float* op0 = out + ((size_t)(b * N_ + R0 + r0)) * (H_ * SUP_) + h * SUP_ + c0;
        float* op1 = op0 + (H_ * SUP_);
        *(float4*)op0 = make_float4(fmaxf(v0.x, 0.f) * inv0, fmaxf(v1.x, 0.f) * inv0,
                                    fmaxf(v2.x, 0.f) * inv0, fmaxf(v3.x, 0.f) * inv0);
        *(float4*)op1 = make_float4(fmaxf(v0.y, 0.f) * inv1, fmaxf(v1.y, 0.f) * inv1,
                                    fmaxf(v2.y, 0.f) * inv1, fmaxf(v3.y, 0.f) * inv1);
    }
}

// ============================================================
extern "C" void kernel_launch(void* const* d_in, const int* in_sizes, int n_in,
                              void* d_out, int out_size){
    // match inputs by element count: A=8388608, X=4194304, W=262144, w1/w2=512, b1/b2=8
    const float *A = nullptr, *X = nullptr, *W = nullptr;
    const float *w1 = nullptr, *w2 = nullptr, *b1 = nullptr, *b2 = nullptr;
    for (int i = 0; i < n_in; i++){
        const float* p = (const float*)d_in[i];
        switch (in_sizes[i]){
            case 8388608: A = p; break;
            case 4194304: X = p; break;
            case 262144:  W = p; break;
            case 512:     (w1 ? w2 : w1) = p; break;
            case 8:       (b1 ? b2 : b1) = p; break;
            default: break;
        }
    }
    float* out = (float*)d_out;

    cudaFuncSetAttribute(proj_mma_kernel, cudaFuncAttributeMaxDynamicSharedMemorySize, PROJ_SMEM);

    cvtx_kernel<<<ROWS_ * IN_ / 4 / 256, 256>>>(X);
    cvtw_kernel<<<dim3(SUP_, H_), 128>>>(W);
    proj_mma_kernel<<<dim3(ROWS_ / 128, H_), 256, PROJ_SMEM>>>(out);
    fc_kernel<<<BH_ * N_ / 8, 256>>>(w1, b1, w2, b2);
    attn_kernel<<<dim3(N_ / 128, BH_), 256>>>(A, out);
}